// round 1
// baseline (speedup 1.0000x reference)
#include <cuda_runtime.h>
#include <cuda_bf16.h>

#define NODES_MAX 50000
#define CC 64
#define HID 128

// Scratch for per-node MLP outputs (no allocations allowed).
__device__ float g_p[NODES_MAX * CC];
__device__ float g_q[NODES_MAX * CC];

// Shared-mem layout (floats):
//   W1p[64*128] W2p[128*64] W1q[64*128] W2q[128*64]   = 32768
//   b1p[128] b2p[64] b1q[128] b2q[64]                 = 384
//   ls[64] lb[64]                                     = 128
//   per-warp buffers: NWARPS * (64 xn + 128 h)        = NWARPS*192
#define NODE_THREADS 512
#define NODE_WARPS (NODE_THREADS / 32)
#define SMEM_FLOATS (4 * CC * HID + 2 * (HID + CC) + 2 * CC + NODE_WARPS * (CC + HID))
#define SMEM_BYTES (SMEM_FLOATS * 4)

__device__ __forceinline__ void warp_mlp(
    const float* __restrict__ xn,   // smem [64]
    float* __restrict__ h,          // smem [128]
    const float* __restrict__ W1,   // smem [64*128]
    const float* __restrict__ b1,   // smem [128]
    const float* __restrict__ W2,   // smem [128*64]
    const float* __restrict__ b2,   // smem [64]
    float* __restrict__ out,        // gmem [64]
    int lane)
{
    // Layer 1: each lane computes 4 of 128 hidden units.
    float4 acc = *(const float4*)&b1[4 * lane];
    #pragma unroll 8
    for (int k = 0; k < CC; k++) {
        float xk = xn[k];
        float4 w = *(const float4*)&W1[k * HID + 4 * lane];
        acc.x += xk * w.x; acc.y += xk * w.y;
        acc.z += xk * w.z; acc.w += xk * w.w;
    }
    // SiLU
    acc.x = acc.x / (1.f + __expf(-acc.x));
    acc.y = acc.y / (1.f + __expf(-acc.y));
    acc.z = acc.z / (1.f + __expf(-acc.z));
    acc.w = acc.w / (1.f + __expf(-acc.w));
    *(float4*)&h[4 * lane] = acc;
    __syncwarp();

    // Layer 2: each lane computes 2 of 64 outputs.
    float2 a2 = *(const float2*)&b2[2 * lane];
    #pragma unroll 8
    for (int k = 0; k < HID; k++) {
        float hk = h[k];
        float2 w = *(const float2*)&W2[k * CC + 2 * lane];
        a2.x += hk * w.x; a2.y += hk * w.y;
    }
    *(float2*)&out[2 * lane] = a2;
    __syncwarp();   // protect h before next MLP overwrites it
}

__global__ void __launch_bounds__(NODE_THREADS, 1)
node_kernel(const float* __restrict__ x,
            const float* __restrict__ ln_scale, const float* __restrict__ ln_bias,
            const float* __restrict__ p_w1, const float* __restrict__ p_b1,
            const float* __restrict__ p_w2, const float* __restrict__ p_b2,
            const float* __restrict__ q_w1, const float* __restrict__ q_b1,
            const float* __restrict__ q_w2, const float* __restrict__ q_b2,
            int nnodes)
{
    extern __shared__ float smem[];
    float* sW1p = smem;
    float* sW2p = sW1p + CC * HID;
    float* sW1q = sW2p + HID * CC;
    float* sW2q = sW1q + CC * HID;
    float* sb1p = sW2q + HID * CC;
    float* sb2p = sb1p + HID;
    float* sb1q = sb2p + CC;
    float* sb2q = sb1q + HID;
    float* sls  = sb2q + CC;
    float* slb  = sls + CC;
    float* sbuf = slb + CC;

    int tid = threadIdx.x;
    for (int i = tid; i < CC * HID; i += NODE_THREADS) {
        sW1p[i] = p_w1[i]; sW1q[i] = q_w1[i];
        sW2p[i] = p_w2[i]; sW2q[i] = q_w2[i];
    }
    for (int i = tid; i < HID; i += NODE_THREADS) { sb1p[i] = p_b1[i]; sb1q[i] = q_b1[i]; }
    for (int i = tid; i < CC; i += NODE_THREADS) {
        sb2p[i] = p_b2[i]; sb2q[i] = q_b2[i];
        sls[i] = ln_scale[i]; slb[i] = ln_bias[i];
    }
    __syncthreads();

    int warp = tid >> 5, lane = tid & 31;
    float* w_xn = sbuf + warp * (CC + HID);
    float* w_h  = w_xn + CC;

    for (int n = blockIdx.x * NODE_WARPS + warp; n < nnodes;
         n += gridDim.x * NODE_WARPS) {
        float2 xv = *(const float2*)&x[n * CC + 2 * lane];
        float s  = xv.x + xv.y;
        float ss = xv.x * xv.x + xv.y * xv.y;
        #pragma unroll
        for (int o = 16; o > 0; o >>= 1) {
            s  += __shfl_xor_sync(0xFFFFFFFFu, s,  o);
            ss += __shfl_xor_sync(0xFFFFFFFFu, ss, o);
        }
        float mean = s * (1.f / CC);
        float var  = ss * (1.f / CC) - mean * mean;
        float rstd = rsqrtf(var + 1e-5f);
        float xn0 = (xv.x - mean) * rstd * sls[2 * lane]     + slb[2 * lane];
        float xn1 = (xv.y - mean) * rstd * sls[2 * lane + 1] + slb[2 * lane + 1];
        *(float2*)&w_xn[2 * lane] = make_float2(xn0, xn1);
        __syncwarp();

        warp_mlp(w_xn, w_h, sW1p, sb1p, sW2p, sb2p, &g_p[n * CC], lane);
        warp_mlp(w_xn, w_h, sW1q, sb1q, sW2q, sb2q, &g_q[n * CC], lane);
    }
}

// One warp per edge; lane handles channels (2*lane, 2*lane+1).
__global__ void __launch_bounds__(256)
edge_kernel(const float* __restrict__ vec,
            const float* __restrict__ im,       // [E,3,3]
            const float* __restrict__ vln,      // [64]
            const int*   __restrict__ senders,
            const int*   __restrict__ receivers,
            float* __restrict__ dvec,           // [N,3,64]
            int nedges)
{
    int e = (blockIdx.x * blockDim.x + threadIdx.x) >> 5;
    int lane = threadIdx.x & 31;
    if (e >= nedges) return;

    int s = __ldg(&senders[e]);
    int r = __ldg(&receivers[e]);

    const float* Me = im + (size_t)e * 9;
    float m00 = __ldg(Me + 0), m01 = __ldg(Me + 1), m02 = __ldg(Me + 2);
    float m10 = __ldg(Me + 3), m11 = __ldg(Me + 4), m12 = __ldg(Me + 5);
    float m20 = __ldg(Me + 6), m21 = __ldg(Me + 7), m22 = __ldg(Me + 8);

    int c = 2 * lane;
    float2 q2 = *(const float2*)&g_q[(size_t)s * CC + c];
    float2 p2 = *(const float2*)&g_p[(size_t)r * CC + c];
    float2 vw = *(const float2*)&vln[c];

    const float* vbase = vec + (size_t)s * 3 * CC + c;
    float2 v0 = *(const float2*)(vbase);
    float2 v1 = *(const float2*)(vbase + CC);
    float2 v2 = *(const float2*)(vbase + 2 * CC);

    // scaled_j = q_j * vln * vec_j
    float sx0 = q2.x * vw.x * v0.x, sy0 = q2.y * vw.y * v0.y;
    float sx1 = q2.x * vw.x * v1.x, sy1 = q2.y * vw.y * v1.y;
    float sx2 = q2.x * vw.x * v2.x, sy2 = q2.y * vw.y * v2.y;

    // induced[i] = sum_j M[i][j] * scaled[j]; messages = p_i * induced
    float ix0 = p2.x * (m00 * sx0 + m01 * sx1 + m02 * sx2);
    float iy0 = p2.y * (m00 * sy0 + m01 * sy1 + m02 * sy2);
    float ix1 = p2.x * (m10 * sx0 + m11 * sx1 + m12 * sx2);
    float iy1 = p2.y * (m10 * sy0 + m11 * sy1 + m12 * sy2);
    float ix2 = p2.x * (m20 * sx0 + m21 * sx1 + m22 * sx2);
    float iy2 = p2.y * (m20 * sy0 + m21 * sy1 + m22 * sy2);

    float* dbase = dvec + (size_t)r * 3 * CC + c;
    asm volatile("red.global.add.v2.f32 [%0], {%1, %2};"
                 :: "l"(dbase),            "f"(ix0), "f"(iy0) : "memory");
    asm volatile("red.global.add.v2.f32 [%0], {%1, %2};"
                 :: "l"(dbase + CC),       "f"(ix1), "f"(iy1) : "memory");
    asm volatile("red.global.add.v2.f32 [%0], {%1, %2};"
                 :: "l"(dbase + 2 * CC),   "f"(ix2), "f"(iy2) : "memory");
}

extern "C" void kernel_launch(void* const* d_in, const int* in_sizes, int n_in,
                              void* d_out, int out_size)
{
    const float* x         = (const float*)d_in[0];
    const float* vec       = (const float*)d_in[1];
    const float* im        = (const float*)d_in[2];
    const float* ln_scale  = (const float*)d_in[3];
    const float* ln_bias   = (const float*)d_in[4];
    const float* vln       = (const float*)d_in[5];
    const float* p_w1      = (const float*)d_in[6];
    const float* p_b1      = (const float*)d_in[7];
    const float* p_w2      = (const float*)d_in[8];
    const float* p_b2      = (const float*)d_in[9];
    const float* q_w1      = (const float*)d_in[10];
    const float* q_b1      = (const float*)d_in[11];
    const float* q_w2      = (const float*)d_in[12];
    const float* q_b2      = (const float*)d_in[13];
    const int*   senders   = (const int*)d_in[14];
    const int*   receivers = (const int*)d_in[15];

    int nnodes = in_sizes[0] / CC;
    int nedges = in_sizes[14];

    float* dvec = (float*)d_out;
    cudaMemsetAsync(d_out, 0, (size_t)out_size * sizeof(float), 0);

    cudaFuncSetAttribute(node_kernel,
                         cudaFuncAttributeMaxDynamicSharedMemorySize, SMEM_BYTES);
    node_kernel<<<148, NODE_THREADS, SMEM_BYTES>>>(
        x, ln_scale, ln_bias,
        p_w1, p_b1, p_w2, p_b2,
        q_w1, q_b1, q_w2, q_b2, nnodes);

    int warps_per_block = 256 / 32;
    int blocks = (nedges + warps_per_block - 1) / warps_per_block;
    edge_kernel<<<blocks, 256>>>(vec, im, vln, senders, receivers, dvec, nedges);
}

// round 2
// speedup vs baseline: 1.4067x; 1.4067x over previous
#include <cuda_runtime.h>
#include <cuda_bf16.h>

#define NODES_MAX 50000
#define CC 64
#define HID 128
#define T 8                      // nodes per warp in node kernel

__device__ float g_p[NODES_MAX * CC];
__device__ float g_q[NODES_MAX * CC];

#define NODE_THREADS 384
#define NODE_WARPS (NODE_THREADS / 32)
// smem: 4 weight mats (4*8192) + biases (384) + ls/lb/vln (192) + per-warp bufs
#define BUF_FLOATS (T * (CC + HID))
#define SMEM_FLOATS (4 * CC * HID + 2 * (HID + CC) + 3 * CC + NODE_WARPS * BUF_FLOATS)
#define SMEM_BYTES (SMEM_FLOATS * 4)

// One warp computes an MLP (64 -> 128 silu -> 64) for T nodes at once.
// xn: smem [T][64]; h: smem [T][128] scratch; out: gmem base; scale: per-channel
// multiplier in smem (or nullptr).
__device__ __forceinline__ void warp_mlp_T(
    const float* __restrict__ xn, float* __restrict__ h,
    const float* __restrict__ W1, const float* __restrict__ b1,
    const float* __restrict__ W2, const float* __restrict__ b2,
    float* __restrict__ out, const float* __restrict__ scale,
    int g, int nnodes, int lane)
{
    // ---- layer 1: each lane owns hidden units [4*lane, 4*lane+4) for all T nodes
    float4 acc[T];
    float4 bb = *(const float4*)&b1[4 * lane];
    #pragma unroll
    for (int t = 0; t < T; t++) acc[t] = bb;

    #pragma unroll 2
    for (int k = 0; k < CC; k++) {
        float4 w = *(const float4*)&W1[k * HID + 4 * lane];
        #pragma unroll
        for (int t = 0; t < T; t++) {
            float xk = xn[t * CC + k];
            acc[t].x += xk * w.x; acc[t].y += xk * w.y;
            acc[t].z += xk * w.z; acc[t].w += xk * w.w;
        }
    }
    #pragma unroll
    for (int t = 0; t < T; t++) {
        acc[t].x = acc[t].x / (1.f + __expf(-acc[t].x));
        acc[t].y = acc[t].y / (1.f + __expf(-acc[t].y));
        acc[t].z = acc[t].z / (1.f + __expf(-acc[t].z));
        acc[t].w = acc[t].w / (1.f + __expf(-acc[t].w));
        *(float4*)&h[t * HID + 4 * lane] = acc[t];
    }
    __syncwarp();

    // ---- layer 2: each lane owns output channels {2*lane, 2*lane+1}
    float2 a2[T];
    float2 b2v = *(const float2*)&b2[2 * lane];
    #pragma unroll
    for (int t = 0; t < T; t++) a2[t] = b2v;

    #pragma unroll 2
    for (int k = 0; k < HID; k++) {
        float2 w = *(const float2*)&W2[k * CC + 2 * lane];
        #pragma unroll
        for (int t = 0; t < T; t++) {
            float hk = h[t * HID + k];
            a2[t].x += hk * w.x; a2[t].y += hk * w.y;
        }
    }
    float2 sc = make_float2(1.f, 1.f);
    if (scale) sc = *(const float2*)&scale[2 * lane];
    #pragma unroll
    for (int t = 0; t < T; t++) {
        int n = g + t;
        if (n < nnodes) {
            float2 o = make_float2(a2[t].x * sc.x, a2[t].y * sc.y);
            *(float2*)&out[(size_t)n * CC + 2 * lane] = o;
        }
    }
    __syncwarp();
}

__global__ void __launch_bounds__(NODE_THREADS, 1)
node_kernel(const float* __restrict__ x,
            const float* __restrict__ ln_scale, const float* __restrict__ ln_bias,
            const float* __restrict__ vln,
            const float* __restrict__ p_w1, const float* __restrict__ p_b1,
            const float* __restrict__ p_w2, const float* __restrict__ p_b2,
            const float* __restrict__ q_w1, const float* __restrict__ q_b1,
            const float* __restrict__ q_w2, const float* __restrict__ q_b2,
            int nnodes)
{
    extern __shared__ float smem[];
    float* sW1p = smem;
    float* sW2p = sW1p + CC * HID;
    float* sW1q = sW2p + HID * CC;
    float* sW2q = sW1q + CC * HID;
    float* sb1p = sW2q + HID * CC;
    float* sb2p = sb1p + HID;
    float* sb1q = sb2p + CC;
    float* sb2q = sb1q + HID;
    float* sls  = sb2q + CC;
    float* slb  = sls + CC;
    float* svln = slb + CC;
    float* sbuf = svln + CC;

    int tid = threadIdx.x;
    for (int i = tid; i < CC * HID; i += NODE_THREADS) {
        sW1p[i] = p_w1[i]; sW1q[i] = q_w1[i];
        sW2p[i] = p_w2[i]; sW2q[i] = q_w2[i];
    }
    for (int i = tid; i < HID; i += NODE_THREADS) { sb1p[i] = p_b1[i]; sb1q[i] = q_b1[i]; }
    for (int i = tid; i < CC; i += NODE_THREADS) {
        sb2p[i] = p_b2[i]; sb2q[i] = q_b2[i];
        sls[i] = ln_scale[i]; slb[i] = ln_bias[i]; svln[i] = vln[i];
    }
    __syncthreads();

    int warp = tid >> 5, lane = tid & 31;
    float* w_xn = sbuf + warp * BUF_FLOATS;
    float* w_h  = w_xn + T * CC;

    int gwarp = blockIdx.x * NODE_WARPS + warp;
    int gstride = gridDim.x * NODE_WARPS;
    float2 lsv = *(const float2*)&sls[2 * lane];
    float2 lbv = *(const float2*)&slb[2 * lane];

    for (int g = gwarp * T; g < nnodes; g += gstride * T) {
        // LayerNorm for T nodes
        #pragma unroll
        for (int t = 0; t < T; t++) {
            int n = g + t; if (n >= nnodes) n = nnodes - 1;
            float2 xv = *(const float2*)&x[(size_t)n * CC + 2 * lane];
            float s  = xv.x + xv.y;
            float ss = xv.x * xv.x + xv.y * xv.y;
            #pragma unroll
            for (int o = 16; o > 0; o >>= 1) {
                s  += __shfl_xor_sync(0xFFFFFFFFu, s,  o);
                ss += __shfl_xor_sync(0xFFFFFFFFu, ss, o);
            }
            float mean = s * (1.f / CC);
            float var  = ss * (1.f / CC) - mean * mean;
            float rstd = rsqrtf(var + 1e-5f);
            float xn0 = (xv.x - mean) * rstd * lsv.x + lbv.x;
            float xn1 = (xv.y - mean) * rstd * lsv.y + lbv.y;
            *(float2*)&w_xn[t * CC + 2 * lane] = make_float2(xn0, xn1);
        }
        __syncwarp();

        warp_mlp_T(w_xn, w_h, sW1p, sb1p, sW2p, sb2p, g_p, nullptr, g, nnodes, lane);
        warp_mlp_T(w_xn, w_h, sW1q, sb1q, sW2q, sb2q, g_q, svln,   g, nnodes, lane);
    }
}

// One warp per edge; lane handles channels (2*lane, 2*lane+1).
// Accumulates induced_field (p applied in epilogue; vln already folded into g_q).
__global__ void __launch_bounds__(256)
edge_kernel(const float* __restrict__ vec,
            const float* __restrict__ im,       // [E,3,3]
            const int*   __restrict__ senders,
            const int*   __restrict__ receivers,
            float* __restrict__ dvec,           // [N,3,64]
            int nedges)
{
    int e = (blockIdx.x * blockDim.x + threadIdx.x) >> 5;
    int lane = threadIdx.x & 31;
    if (e >= nedges) return;

    int s = __ldg(&senders[e]);
    int r = __ldg(&receivers[e]);

    const float* Me = im + (size_t)e * 9;
    float m00 = __ldg(Me + 0), m01 = __ldg(Me + 1), m02 = __ldg(Me + 2);
    float m10 = __ldg(Me + 3), m11 = __ldg(Me + 4), m12 = __ldg(Me + 5);
    float m20 = __ldg(Me + 6), m21 = __ldg(Me + 7), m22 = __ldg(Me + 8);

    int c = 2 * lane;
    float2 q2 = *(const float2*)&g_q[(size_t)s * CC + c];

    const float* vbase = vec + (size_t)s * 3 * CC + c;
    float2 v0 = *(const float2*)(vbase);
    float2 v1 = *(const float2*)(vbase + CC);
    float2 v2 = *(const float2*)(vbase + 2 * CC);

    float sx0 = q2.x * v0.x, sy0 = q2.y * v0.y;
    float sx1 = q2.x * v1.x, sy1 = q2.y * v1.y;
    float sx2 = q2.x * v2.x, sy2 = q2.y * v2.y;

    float ix0 = m00 * sx0 + m01 * sx1 + m02 * sx2;
    float iy0 = m00 * sy0 + m01 * sy1 + m02 * sy2;
    float ix1 = m10 * sx0 + m11 * sx1 + m12 * sx2;
    float iy1 = m10 * sy0 + m11 * sy1 + m12 * sy2;
    float ix2 = m20 * sx0 + m21 * sx1 + m22 * sx2;
    float iy2 = m20 * sy0 + m21 * sy1 + m22 * sy2;

    float* dbase = dvec + (size_t)r * 3 * CC + c;
    asm volatile("red.global.add.v2.f32 [%0], {%1, %2};"
                 :: "l"(dbase),          "f"(ix0), "f"(iy0) : "memory");
    asm volatile("red.global.add.v2.f32 [%0], {%1, %2};"
                 :: "l"(dbase + CC),     "f"(ix1), "f"(iy1) : "memory");
    asm volatile("red.global.add.v2.f32 [%0], {%1, %2};"
                 :: "l"(dbase + 2 * CC), "f"(ix2), "f"(iy2) : "memory");
}

// dvec[n][i][:] *= p[n][:]
__global__ void __launch_bounds__(256)
epilogue_kernel(float* __restrict__ dvec, int nnodes)
{
    int idx = blockIdx.x * blockDim.x + threadIdx.x;
    int n = idx >> 5;
    if (n >= nnodes) return;
    int c = (idx & 31) * 2;
    float2 p2 = *(const float2*)&g_p[(size_t)n * CC + c];
    float* dbase = dvec + (size_t)n * 3 * CC + c;
    #pragma unroll
    for (int i = 0; i < 3; i++) {
        float2 d = *(float2*)(dbase + i * CC);
        d.x *= p2.x; d.y *= p2.y;
        *(float2*)(dbase + i * CC) = d;
    }
}

extern "C" void kernel_launch(void* const* d_in, const int* in_sizes, int n_in,
                              void* d_out, int out_size)
{
    const float* x         = (const float*)d_in[0];
    const float* vec       = (const float*)d_in[1];
    const float* im        = (const float*)d_in[2];
    const float* ln_scale  = (const float*)d_in[3];
    const float* ln_bias   = (const float*)d_in[4];
    const float* vln       = (const float*)d_in[5];
    const float* p_w1      = (const float*)d_in[6];
    const float* p_b1      = (const float*)d_in[7];
    const float* p_w2      = (const float*)d_in[8];
    const float* p_b2      = (const float*)d_in[9];
    const float* q_w1      = (const float*)d_in[10];
    const float* q_b1      = (const float*)d_in[11];
    const float* q_w2      = (const float*)d_in[12];
    const float* q_b2      = (const float*)d_in[13];
    const int*   senders   = (const int*)d_in[14];
    const int*   receivers = (const int*)d_in[15];

    int nnodes = in_sizes[0] / CC;
    int nedges = in_sizes[14];

    float* dvec = (float*)d_out;
    cudaMemsetAsync(d_out, 0, (size_t)out_size * sizeof(float), 0);

    cudaFuncSetAttribute(node_kernel,
                         cudaFuncAttributeMaxDynamicSharedMemorySize, SMEM_BYTES);
    node_kernel<<<148, NODE_THREADS, SMEM_BYTES>>>(
        x, ln_scale, ln_bias, vln,
        p_w1, p_b1, p_w2, p_b2,
        q_w1, q_b1, q_w2, q_b2, nnodes);

    int warps_per_block = 256 / 32;
    int eblocks = (nedges + warps_per_block - 1) / warps_per_block;
    edge_kernel<<<eblocks, 256>>>(vec, im, senders, receivers, dvec, nedges);

    int nthreads = nnodes * 32;
    epilogue_kernel<<<(nthreads + 255) / 256, 256>>>(dvec, nnodes);
}